// round 17
// baseline (speedup 1.0000x reference)
#include <cuda_runtime.h>
#include <cuda_fp16.h>

// SpatialGraphConv fused (fp16 mma.m16n8k16 main GEMM, fp32 accum).
// out[n,o,m] = relu( sum_c W[o,c]*Z[c,m] + bo[o] + g1b[o]*sumAe[m%25] )
//   Z rows 0..63  = x (res branch), rows 64..127 = xA = x@Ae (gcn branch)
// 148 CTAs x 512 thr, ONE tile stream per CTA, double-buffered raw & Zq images,
// ONE __syncthreads per tile: convert/stage1 of tile t+1 overlap (at warp
// granularity) with main MMA / epilogue of tile t.
// Zq = qword image [r=s*4+tig][col]: low word b0 / high word b1 of fp16 B-frag
// (1 LDS.64 per frag). W pre-baked in A-frag order (1 LDS.128 per frag).

#define NTILES (64*60)
#define MTOT   7500
#define RS     132      // raw x row stride (floats)
#define QS     132      // Zq row stride (qwords; word-stride 264 % 32 == 8)
#define AS     40       // Ae row stride

__device__ __align__(16) __half g_Whf[16384];  // fp16 W in m16n8k16 A-frag order
__device__ float g_bo[128];
__device__ float g_g1b[128];
__device__ float g_Ae32[1024];                 // tf32 bits, zero-padded 32x32
__device__ float g_sumAe[32];

static __device__ __forceinline__ void mma_tf32(float* c, const unsigned* a, const unsigned* b) {
    asm volatile(
        "mma.sync.aligned.m16n8k8.row.col.f32.tf32.tf32.f32 "
        "{%0,%1,%2,%3}, {%4,%5,%6,%7}, {%8,%9}, {%0,%1,%2,%3};"
        : "+f"(c[0]), "+f"(c[1]), "+f"(c[2]), "+f"(c[3])
        : "r"(a[0]), "r"(a[1]), "r"(a[2]), "r"(a[3]), "r"(b[0]), "r"(b[1]));
}
static __device__ __forceinline__ void mma_f16(float* c, const unsigned* a,
                                               unsigned b0, unsigned b1) {
    asm volatile(
        "mma.sync.aligned.m16n8k16.row.col.f32.f16.f16.f32 "
        "{%0,%1,%2,%3}, {%4,%5,%6,%7}, {%8,%9}, {%0,%1,%2,%3};"
        : "+f"(c[0]), "+f"(c[1]), "+f"(c[2]), "+f"(c[3])
        : "r"(a[0]), "r"(a[1]), "r"(a[2]), "r"(a[3]), "r"(b0), "r"(b1));
}
static __device__ __forceinline__ unsigned tf32_bits(float f) {
    unsigned u; asm("cvt.rna.tf32.f32 %0, %1;" : "=r"(u) : "f"(f)); return u;
}
static __device__ __forceinline__ unsigned pack_h2(float lo, float hi) {
    __half2 h = __floats2half2_rn(lo, hi);
    return *reinterpret_cast<unsigned*>(&h);
}

// ---------------- prep ----------------
__global__ void prep_kernel(const float* __restrict__ A, const float* __restrict__ edge,
                            const float* __restrict__ gcn_w, const float* __restrict__ gcn_b,
                            const float* __restrict__ bn_g, const float* __restrict__ bn_b,
                            const float* __restrict__ bn_m, const float* __restrict__ bn_v,
                            const float* __restrict__ res_w, const float* __restrict__ res_b,
                            const float* __restrict__ rbn_g, const float* __restrict__ rbn_b,
                            const float* __restrict__ rbn_m, const float* __restrict__ rbn_v) {
    int b = blockIdx.x, tid = threadIdx.x;
    if (b < 128) {
        int o = b;
        float inv1 = bn_g[o]  * rsqrtf(bn_v[o]  + 1e-5f);
        float inv2 = rbn_g[o] * rsqrtf(rbn_v[o] + 1e-5f);
        float wr = inv2 * res_w[o*64 + tid];   // k = tid       (res)
        float wg = inv1 * gcn_w[o*64 + tid];   // k = tid + 64  (gcn)
        #pragma unroll
        for (int s = 0; s < 2; s++) {
            int k = tid + s*64;
            float w = s ? wg : wr;
            int ks = k >> 4, o16 = o >> 4, orow = o & 15;
            int gidp = orow & 7, rh = orow >> 3;
            int kin = k & 15, kh = kin >> 3, tg2 = (kin & 7) >> 1, par = kin & 1;
            int idx = ((((ks*8 + o16)*32 + gidp*4 + tg2) << 2) + (rh + 2*kh)) * 2 + par;
            g_Whf[idx] = __float2half_rn(w);
        }
        if (tid == 0) {
            float sh1 = bn_b[o]  - bn_m[o]  * inv1;
            float sh2 = rbn_b[o] - rbn_m[o] * inv2;
            g_bo[o]  = sh1 + sh2 + inv2 * res_b[o];
            g_g1b[o] = inv1 * gcn_b[o];
        }
    } else if (b == 128) {
        for (int i = tid; i < 1024; i += 64) {
            int v = i >> 5, w = i & 31;
            g_Ae32[i] = (v < 25 && w < 25)
                ? __uint_as_float(tf32_bits(A[v*25 + w] * edge[v*25 + w])) : 0.f;
        }
    } else {
        if (tid < 32) {
            float s = 0.f;
            if (tid < 25)
                for (int v = 0; v < 25; v++) s += A[v*25 + tid] * edge[v*25 + tid];
            g_sumAe[tid] = s;
        }
    }
}

// ---------------- fused persistent kernel ----------------
// smem floats: Wh | raw0 | raw1 | Zq0 | Zq1 | Ae | bo | g1b | sum | scol
#define SWH_OFF   0                       // 8192
#define XBR_OFF(b) (8192  + (b)*8448)     // raw 64*132 floats
#define ZQ_OFF(b)  (25088 + (b)*8448)     // Zq 32*132 qwords = 8448 floats
#define AE_OFF    41984
#define BO_OFF    (AE_OFF + 32*AS)        // 43264
#define G1_OFF    (BO_OFF + 128)
#define SUM_OFF   (G1_OFF + 128)
#define SCOL_OFF  (SUM_OFF + 32)          // 4 x 128
#define SMEM_FLOATS (SCOL_OFF + 512)      // 44064 -> 176256 B

extern __shared__ float smem[];

static __device__ __forceinline__ void issue_tile(const float* __restrict__ x,
                                                  float* __restrict__ raw, int t, int tid) {
    int n = t / 60, mt = t - n * 60;
    int m0a = (mt * 125) & ~3;            // 16B-aligned, m0a+128 <= 7500
    const float* src = x + (size_t)n * 64 * MTOT + m0a;
    #pragma unroll
    for (int j = 0; j < 4; j++) {
        int i = tid + 512 * j;            // < 2048 float4 chunks
        int c = i >> 5, q = (i & 31) * 4;
        const float* g = src + (size_t)c * MTOT + q;
        unsigned sa = (unsigned)__cvta_generic_to_shared(raw + c * RS + q);
        asm volatile("cp.async.cg.shared.global [%0], [%1], 16;\n" :: "r"(sa), "l"(g));
    }
}

__global__ __launch_bounds__(512, 1) void fused_kernel(const float* __restrict__ x,
                                                       float* __restrict__ out) {
    int tid = threadIdx.x, lane = tid & 31, wid = tid >> 5;  // 16 warps
    int gid = lane >> 2, tig = lane & 3;
    int ow = wid & 3, mw = wid >> 2;      // 4 o-warps x 4 m-warps
    int ob = ow * 32, mb = mw * 32;

    float*    sAe = smem + AE_OFF;
    unsigned* sAeU = reinterpret_cast<unsigned*>(sAe);

    // ---- one-time init ----
    for (int i = tid; i < 2048; i += 512)   // W frags (32KB)
        *reinterpret_cast<uint4*>(&smem[SWH_OFF + i*4]) =
            reinterpret_cast<const uint4*>(g_Whf)[i];
    for (int i = tid; i < 1024; i += 512)
        sAe[(i >> 5) * AS + (i & 31)] = g_Ae32[i];
    if (tid < 128) { smem[BO_OFF + tid] = g_bo[tid]; smem[G1_OFF + tid] = g_g1b[tid]; }
    if (tid < 32)  { smem[SUM_OFF + tid] = g_sumAe[tid]; }
    for (int i = tid; i < 512; i += 512) {
        int d = i >> 7, sc = i & 127;       // scol[d][sc] = sumAe[(sc-d) mod 25]
        int w = sc - d; w %= 25; if (w < 0) w += 25;
        smem[SCOL_OFF + i] = g_sumAe[w];
    }
    for (int j = tid; j < 512; j += 512) {  // raw pad cols 128..131 = 0 (both bufs)
        int b = j >> 8, jj = j & 255;
        smem[XBR_OFF(b) + (jj >> 2) * RS + 128 + (jj & 3)] = 0.f;
    }
    for (int j = tid; j < 256; j += 512) {  // Zq pad qword cols 128..131 = 0 (both)
        int b = j >> 7, jj = j & 127;
        int r = jj >> 2, qc = 128 + (jj & 3);
        unsigned* zp = reinterpret_cast<unsigned*>(smem + ZQ_OFF(b));
        zp[(r * QS + qc) * 2]     = 0u;
        zp[(r * QS + qc) * 2 + 1] = 0u;
    }
    __syncthreads();

    // =================== per-tile phase helpers ===================
    #define CONVERT(RAWP, ZB) do {                                                   \
        float* xbr_ = (RAWP);                                                        \
        unsigned* zq_ = reinterpret_cast<unsigned*>(smem + ZQ_OFF(ZB));              \
        _Pragma("unroll")                                                            \
        for (int it = 0; it < 2; it++) {                                             \
            int u = tid + 512 * it;          /* < 1024 */                             \
            int r = u >> 6, c2 = u & 63;                                             \
            int R0 = ((r >> 2) << 4) + ((r & 3) << 1);                               \
            int cw = c2 * 2;                                                         \
            float2 va = *reinterpret_cast<float2*>(&xbr_[(R0    ) * RS + cw]);       \
            float2 vb = *reinterpret_cast<float2*>(&xbr_[(R0 + 1) * RS + cw]);       \
            float2 vc = *reinterpret_cast<float2*>(&xbr_[(R0 + 8) * RS + cw]);       \
            float2 vd = *reinterpret_cast<float2*>(&xbr_[(R0 + 9) * RS + cw]);       \
            uint4 w;                                                                 \
            w.x = pack_h2(va.x, vb.x); w.y = pack_h2(vc.x, vd.x);                    \
            w.z = pack_h2(va.y, vb.y); w.w = pack_h2(vc.y, vd.y);                    \
            *reinterpret_cast<uint4*>(&zq_[(r * QS + cw) * 2]) = w;                  \
        }                                                                            \
    } while (0)

    #define STAGE1(RAWP, ZB, DLT) do {                                              \
        float* xbr_ = (RAWP);                                                        \
        __half* zqH_ = reinterpret_cast<__half*>(smem + ZQ_OFF(ZB));                 \
        for (int u = wid; u < 20; u += 16) {                                         \
            int tg = u >> 2, m16 = u & 3;                                            \
            int r0 = m16 * 16 + gid;                                                 \
            float a1[4][4];                                                          \
            _Pragma("unroll")                                                        \
            for (int nt = 0; nt < 4; nt++)                                           \
                _Pragma("unroll")                                                    \
                for (int q = 0; q < 4; q++) a1[nt][q] = 0.f;                         \
            _Pragma("unroll")                                                        \
            for (int k8 = 0; k8 < 4; k8++) {                                         \
                int cb = tg * 25 + (DLT) + k8 * 8;                                   \
                int c0 = min(cb + tig, 131), c1 = min(cb + tig + 4, 131);            \
                unsigned a[4];                                                       \
                a[0] = __float_as_uint(xbr_[ r0      * RS + c0]);                    \
                a[1] = __float_as_uint(xbr_[(r0 + 8) * RS + c0]);                    \
                a[2] = __float_as_uint(xbr_[ r0      * RS + c1]);                    \
                a[3] = __float_as_uint(xbr_[(r0 + 8) * RS + c1]);                    \
                _Pragma("unroll")                                                    \
                for (int nt = 0; nt < 4; nt++) {                                     \
                    unsigned b2[2];                                                  \
                    b2[0] = sAeU[(k8*8 + tig    ) * AS + nt*8 + gid];                \
                    b2[1] = sAeU[(k8*8 + tig + 4) * AS + nt*8 + gid];                \
                    mma_tf32(a1[nt], a, b2);                                         \
                }                                                                    \
            }                                                                        \
            int colb = tg * 25 + (DLT);                                              \
            int rrA = r0, rrB = r0 + 8;                                              \
            int jA = (rrA & 15) >> 1, jB = (rrB & 15) >> 1;                          \
            int rA = (4 + (rrA >> 4)) * 4 + (jA & 3), hA = jA >> 2, pA = rrA & 1;    \
            int rB = (4 + (rrB >> 4)) * 4 + (jB & 3), hB = jB >> 2, pB = rrB & 1;    \
            _Pragma("unroll")                                                        \
            for (int nt = 0; nt < 4; nt++) {                                         \
                int w0 = nt * 8 + tig * 2;                                           \
                if (w0 < 25) {                                                       \
                    zqH_[((rA*QS + colb + w0)*2 + hA)*2 + pA] = __float2half_rn(a1[nt][0]); \
                    zqH_[((rB*QS + colb + w0)*2 + hB)*2 + pB] = __float2half_rn(a1[nt][2]); \
                }                                                                    \
                if (w0 + 1 < 25) {                                                   \
                    zqH_[((rA*QS + colb + w0+1)*2 + hA)*2 + pA] = __float2half_rn(a1[nt][1]); \
                    zqH_[((rB*QS + colb + w0+1)*2 + hB)*2 + pB] = __float2half_rn(a1[nt][3]); \
                }                                                                    \
            }                                                                        \
        }                                                                            \
    } while (0)

    // ---- prologue ----
    int t = blockIdx.x, step = gridDim.x;
    issue_tile(x, smem + XBR_OFF(0), t, tid);
    asm volatile("cp.async.commit_group;");
    if (t + step < NTILES) issue_tile(x, smem + XBR_OFF(1), t + step, tid);
    asm volatile("cp.async.commit_group;");
    asm volatile("cp.async.wait_group 1;");
    __syncthreads();                          // raw[0] visible to all
    {
        int dlt0 = ((t % 60) * 125) & 3;
        CONVERT(smem + XBR_OFF(0), 0);
        STAGE1(smem + XBR_OFF(0), 0, dlt0);
    }

    int b = 0;
    for (; t < NTILES; t += step, b ^= 1) {
        asm volatile("cp.async.wait_group 0;"); // own copies of raw[b^1] (t+1) done
        __syncthreads();                        // Zq[b] published; Zq[b^1] free; raw visible

        // ---- issue raw(t+2) into raw[b] (its readers finished last iteration) ----
        if (t + 2*step < NTILES) issue_tile(x, smem + XBR_OFF(b), t + 2*step, tid);
        asm volatile("cp.async.commit_group;");

        int n = t / 60, mt = t - n * 60;
        int m0 = mt * 125;
        int dlt = m0 & 3;

        // ---- main MMA: warp tile 32o x 32m, 8 k16-steps ----
        unsigned* zqW = reinterpret_cast<unsigned*>(smem + ZQ_OFF(b));
        float acc[2][4][4];
        #pragma unroll
        for (int i = 0; i < 2; i++)
            #pragma unroll
            for (int j = 0; j < 4; j++)
                #pragma unroll
                for (int q = 0; q < 4; q++) acc[i][j][q] = 0.f;

        #pragma unroll
        for (int s = 0; s < 8; s++) {
            unsigned a[2][4];
            #pragma unroll
            for (int os = 0; os < 2; os++) {
                int o16 = ow * 2 + os;
                uint4 av = *reinterpret_cast<uint4*>(
                    &smem[SWH_OFF + (((s*8 + o16)*32 + lane) << 2)]);
                a[os][0] = av.x; a[os][1] = av.y; a[os][2] = av.z; a[os][3] = av.w;
            }
            int rbase = (s * 4 + tig) * QS;
            #pragma unroll
            for (int ms = 0; ms < 4; ms++) {
                int col = mb + ms * 8 + gid + dlt;
                unsigned long long bq = *reinterpret_cast<const unsigned long long*>(
                    &zqW[(rbase + col) * 2]);
                unsigned b0 = (unsigned)bq, b1 = (unsigned)(bq >> 32);
                mma_f16(acc[0][ms], a[0], b0, b1);
                mma_f16(acc[1][ms], a[1], b0, b1);
            }
        }

        // ---- epilogue: bias via scol table + relu + store ----
        const float* scd = smem + SCOL_OFF + dlt * 128;
        bool vec_ok = ((m0 & 1) == 0);
        #pragma unroll
        for (int os = 0; os < 2; os++) {
            int r0 = ob + os * 16 + gid;
            float bo0 = smem[BO_OFF + r0],     g0 = smem[G1_OFF + r0];
            float bo1 = smem[BO_OFF + r0 + 8], g1 = smem[G1_OFF + r0 + 8];
            size_t base0 = ((size_t)n * 128 + r0) * MTOT + m0;
            size_t base1 = base0 + (size_t)8 * MTOT;
            #pragma unroll
            for (int ms = 0; ms < 4; ms++) {
                int sc = mb + ms * 8 + tig * 2;
                if (sc >= 125) continue;
                float s0 = scd[sc], s1 = scd[sc + 1];
                float v00 = fmaxf(fmaf(g0, s0, acc[os][ms][0] + bo0), 0.f);
                float v01 = fmaxf(fmaf(g0, s1, acc[os][ms][1] + bo0), 0.f);
                float v10 = fmaxf(fmaf(g1, s0, acc[os][ms][2] + bo1), 0.f);
                float v11 = fmaxf(fmaf(g1, s1, acc[os][ms][3] + bo1), 0.f);
                if (vec_ok && sc + 2 <= 125) {
                    *reinterpret_cast<float2*>(&out[base0 + sc]) = make_float2(v00, v01);
                    *reinterpret_cast<float2*>(&out[base1 + sc]) = make_float2(v10, v11);
                } else {
                    out[base0 + sc] = v00;
                    out[base1 + sc] = v10;
                    if (sc + 1 < 125) {
                        out[base0 + sc + 1] = v01;
                        out[base1 + sc + 1] = v11;
                    }
                }
            }
        }

        // ---- prepare tile t+1 into Zq[b^1] (overlaps other warps' main/epi) ----
        if (t + step < NTILES) {
            int dltn = (((t + step) % 60) * 125) & 3;
            CONVERT(smem + XBR_OFF(b ^ 1), b ^ 1);
            STAGE1(smem + XBR_OFF(b ^ 1), b ^ 1, dltn);
        }
    }
}

extern "C" void kernel_launch(void* const* d_in, const int* in_sizes, int n_in,
                              void* d_out, int out_size) {
    const float* x     = (const float*)d_in[0];
    const float* A     = (const float*)d_in[1];
    const float* edge  = (const float*)d_in[2];
    const float* gcn_w = (const float*)d_in[3];
    const float* gcn_b = (const float*)d_in[4];
    const float* bn_g  = (const float*)d_in[5];
    const float* bn_b  = (const float*)d_in[6];
    const float* bn_m  = (const float*)d_in[7];
    const float* bn_v  = (const float*)d_in[8];
    const float* res_w = (const float*)d_in[9];
    const float* res_b = (const float*)d_in[10];
    const float* rbn_g = (const float*)d_in[11];
    const float* rbn_b = (const float*)d_in[12];
    const float* rbn_m = (const float*)d_in[13];
    const float* rbn_v = (const float*)d_in[14];
    float* out = (float*)d_out;

    cudaFuncSetAttribute(fused_kernel, cudaFuncAttributeMaxDynamicSharedMemorySize,
                         SMEM_FLOATS * 4);

    prep_kernel<<<130, 64>>>(A, edge, gcn_w, gcn_b, bn_g, bn_b, bn_m, bn_v,
                             res_w, res_b, rbn_g, rbn_b, rbn_m, rbn_v);
    fused_kernel<<<148, 512, SMEM_FLOATS * 4>>>(x, out);
}